// round 10
// baseline (speedup 1.0000x reference)
#include <cuda_runtime.h>
#include <cuda_fp16.h>
#include <cstdint>

#define M_ROWS (8 * 4096)
#define DIM 1024
#define NQKV 3072
#define NH 4
#define HD 256

#define BM 256
#define BN 128
#define BK 32
#define STAGES 4
#define KITERS (DIM / BK)                 // 32
#define A_BYTES (256 * 80)                // 20480
#define B_BYTES (128 * 80)                // 10240
#define STAGE_BYTES (A_BYTES + B_BYTES)   // 30720
#define GEMM_SMEM (STAGES * STAGE_BYTES)  // 122880

// ---------------- scratch (static device arrays; no allocation) -------------
__device__ __half g_xh[(size_t)M_ROWS * DIM];
__device__ __half g_qkv[(size_t)M_ROWS * NQKV];
__device__ __half g_ah[(size_t)M_ROWS * DIM];
__device__ __half g_wT[4][(size_t)DIM * DIM];
__device__ float  g_bqkv[NQKV];

// ---------------- PTX helpers ------------------------------------------------
__device__ __forceinline__ uint32_t smem_u32(const void* p) {
    uint32_t a;
    asm("{ .reg .u64 t; cvta.to.shared.u64 t, %1; cvt.u32.u64 %0, t; }" : "=r"(a) : "l"(p));
    return a;
}
#define CP16(dst, src) \
    asm volatile("cp.async.cg.shared.global [%0], [%1], 16;" :: "r"(dst), "l"(src))
#define CP_COMMIT() asm volatile("cp.async.commit_group;" ::: "memory")
#define CP_WAIT2()  asm volatile("cp.async.wait_group 2;" ::: "memory")

#define LDSM_X4(r, addr) \
    asm volatile("ldmatrix.sync.aligned.m8n8.x4.shared.b16 {%0,%1,%2,%3}, [%4];" \
        : "=r"((r)[0]), "=r"((r)[1]), "=r"((r)[2]), "=r"((r)[3]) : "r"(addr))

#define MMA16816(d, a, b) \
    asm volatile("mma.sync.aligned.m16n8k16.row.col.f32.f16.f16.f32 " \
        "{%0,%1,%2,%3}, {%4,%5,%6,%7}, {%8,%9}, {%0,%1,%2,%3};" \
        : "+f"((d)[0]), "+f"((d)[1]), "+f"((d)[2]), "+f"((d)[3]) \
        : "r"((a)[0]), "r"((a)[1]), "r"((a)[2]), "r"((a)[3]), "r"((b)[0]), "r"((b)[1]))

// ---------------- fp16 GEMM via mma.sync -------------------------------------
// C[M, ldc] = A[M,1024] @ B^T + bias, A fp16 row-major, B stored [N][K] fp16.
// CTA 256x128, 8 warps (4 over M x 2 over N), warp tile 64x64. 256 threads.
// Doubled M-tile raises MMA-per-crossbar-byte: 512 MMA (1024cyc) vs ~95KB
// smem traffic (~742cyc) per iter -> crossbar no longer the ceiling.
template <bool OUT_HALF>
__global__ void __launch_bounds__(256, 1)
gemm_h(const __half* __restrict__ A, const __half* __restrict__ B,
       const float* __restrict__ bias, void* __restrict__ Cv, int ldc)
{
    extern __shared__ char sm[];
    const uint32_t sbase = smem_u32(sm);

    const int tid = threadIdx.x;
    const int wid = tid >> 5, lane = tid & 31;
    const int warp_m = wid & 3;        // 4 warps over M (64 rows each)
    const int warp_n = wid >> 2;       // 2 warps over N (64 cols each)
    const int rowBase = blockIdx.y * BM;
    const int colBase = blockIdx.x * BN;

    // cp.async mapping: 16B chunks; r0 = 0..63, c0 = 0..3.
    const int r0 = tid >> 2, c0 = tid & 3;
    const __half* gA = A + (size_t)(rowBase + r0) * DIM + c0 * 8;
    const __half* gB = B + (size_t)(colBase + r0) * DIM + c0 * 8;
    const uint32_t sOff = (uint32_t)(r0 * 80 + c0 * 16);

    float acc[4][8][4];
#pragma unroll
    for (int i = 0; i < 4; i++)
#pragma unroll
        for (int j = 0; j < 8; j++)
#pragma unroll
            for (int q = 0; q < 4; q++) acc[i][j][q] = 0.f;

    auto prefetch = [&](int s, int k0) {
        uint32_t sA = sbase + s * STAGE_BYTES;
        uint32_t sB = sA + A_BYTES;
        const __half* pa = gA + k0;
        const __half* pb = gB + k0;
        // A: 256 rows -> 4 chunks/thread at rows r0 + 64j
#pragma unroll
        for (int j = 0; j < 4; j++)
            CP16(sA + sOff + j * 64 * 80, pa + (size_t)j * 64 * DIM);
        // B: 128 rows -> 2 chunks/thread
#pragma unroll
        for (int j = 0; j < 2; j++)
            CP16(sB + sOff + j * 64 * 80, pb + (size_t)j * 64 * DIM);
        CP_COMMIT();
    };

#pragma unroll
    for (int s = 0; s < STAGES - 1; s++) prefetch(s, s * BK);

    // ldmatrix lane addressing (same scheme as R6, warp_m now 0..3)
    const uint32_t aLane = (uint32_t)((warp_m * 64 + (lane & 15)) * 80 + (lane >> 4) * 16);
    const uint32_t bLane = (uint32_t)((warp_n * 64 + (lane & 7) + ((lane >> 4) << 3)) * 80 +
                                      ((lane >> 3) & 1) * 16);

    for (int i = 0; i < KITERS; i++) {
        CP_WAIT2();
        __syncthreads();
        if (i + STAGES - 1 < KITERS) prefetch((i + STAGES - 1) & (STAGES - 1), (i + STAGES - 1) * BK);
        else CP_COMMIT();

        const uint32_t st = sbase + (i & (STAGES - 1)) * STAGE_BYTES;
        const uint32_t aB = st + aLane;
        const uint32_t bB = st + A_BYTES + bLane;
#pragma unroll
        for (int kk = 0; kk < 2; kk++) {
            uint32_t af[4][4], bf[4][4];
#pragma unroll
            for (int mt = 0; mt < 4; mt++) LDSM_X4(af[mt], aB + mt * 16 * 80 + kk * 32);
#pragma unroll
            for (int p = 0; p < 4; p++)  LDSM_X4(bf[p], bB + p * 16 * 80 + kk * 32);
#pragma unroll
            for (int mt = 0; mt < 4; mt++)
#pragma unroll
                for (int nt = 0; nt < 8; nt++)
                    MMA16816(acc[mt][nt], af[mt], bf[nt >> 1] + (nt & 1) * 2);
        }
    }

    // epilogue
#pragma unroll
    for (int mt = 0; mt < 4; mt++) {
        const int row = rowBase + warp_m * 64 + mt * 16 + (lane >> 2);
#pragma unroll
        for (int nt = 0; nt < 8; nt++) {
            const int col = colBase + warp_n * 64 + nt * 8 + (lane & 3) * 2;
            const float bx = bias[col], by = bias[col + 1];
            if (OUT_HALF) {
                __half* C = (__half*)Cv;
                *(__half2*)(C + (size_t)row * ldc + col) =
                    __floats2half2_rn(acc[mt][nt][0] + bx, acc[mt][nt][1] + by);
                *(__half2*)(C + (size_t)(row + 8) * ldc + col) =
                    __floats2half2_rn(acc[mt][nt][2] + bx, acc[mt][nt][3] + by);
            } else {
                float* C = (float*)Cv;
                *(float2*)(C + (size_t)row * ldc + col) =
                    make_float2(acc[mt][nt][0] + bx, acc[mt][nt][1] + by);
                *(float2*)(C + (size_t)(row + 8) * ldc + col) =
                    make_float2(acc[mt][nt][2] + bx, acc[mt][nt][3] + by);
            }
        }
    }
}

// ---------------- conversion kernels -----------------------------------------
__global__ void cvt_f2h(const float4* __restrict__ in, uint2* __restrict__ out, int n4)
{
    for (int i = blockIdx.x * blockDim.x + threadIdx.x; i < n4; i += gridDim.x * blockDim.x) {
        float4 v = in[i];
        __half2 h01 = __floats2half2_rn(v.x, v.y);
        __half2 h23 = __floats2half2_rn(v.z, v.w);
        out[i] = make_uint2(*(uint32_t*)&h01, *(uint32_t*)&h23);
    }
}

// 4 weights: W[K][N] f32 -> WT[N][K] fp16
__global__ void cvt_wT4(const float* __restrict__ W0, const float* __restrict__ W1,
                        const float* __restrict__ W2, const float* __restrict__ W3,
                        __half* __restrict__ T)
{
    __shared__ float tile[32][33];
    const float* W = (blockIdx.z == 0) ? W0 : (blockIdx.z == 1) ? W1 : (blockIdx.z == 2) ? W2 : W3;
    __half* Tz = T + (size_t)blockIdx.z * DIM * DIM;
    int n0 = blockIdx.x * 32, k0 = blockIdx.y * 32;
    int tx = threadIdx.x, ty = threadIdx.y;
#pragma unroll
    for (int j = 0; j < 32; j += 8)
        tile[ty + j][tx] = W[(size_t)(k0 + ty + j) * DIM + n0 + tx];
    __syncthreads();
#pragma unroll
    for (int j = 0; j < 32; j += 8)
        Tz[(size_t)(n0 + ty + j) * DIM + k0 + tx] = __float2half_rn(tile[tx][ty + j]);
}

__global__ void concat_bias(const float* __restrict__ bq, const float* __restrict__ bk,
                            const float* __restrict__ bv, float* __restrict__ o)
{
    int i = blockIdx.x * blockDim.x + threadIdx.x;
    if (i < DIM) {
        o[i] = bq[i];
        o[i + DIM] = bk[i];
        o[i + 2 * DIM] = bv[i];
    }
}

// ---------------- per-node head-head attention: 2 nodes per 256-thr block ----
__global__ __launch_bounds__(256)
void attn_kernel(const __half* __restrict__ QKV, __half* __restrict__ Ah)
{
    __shared__ float sq[2][DIM], sk[2][DIM], sv[2][DIM];
    __shared__ float sw[2][NH][NH];

    const int tid = threadIdx.x;
    const int grp = tid >> 7;            // 0 or 1
    const int gt = tid & 127;
    const int node = blockIdx.x * 2 + grp;

    const __half* q = QKV + (size_t)node * NQKV;
    const __half* k = q + DIM;
    const __half* v = q + 2 * DIM;

    {
        uint4 vq = ((const uint4*)q)[gt];
        uint4 vk = ((const uint4*)k)[gt];
        uint4 vv = ((const uint4*)v)[gt];
        const __half2* hq = (const __half2*)&vq;
        const __half2* hk = (const __half2*)&vk;
        const __half2* hv = (const __half2*)&vv;
#pragma unroll
        for (int j = 0; j < 4; j++) {
            float2 fq = __half22float2(hq[j]);
            float2 fk = __half22float2(hk[j]);
            float2 fv = __half22float2(hv[j]);
            sq[grp][gt * 8 + 2 * j] = fq.x; sq[grp][gt * 8 + 2 * j + 1] = fq.y;
            sk[grp][gt * 8 + 2 * j] = fk.x; sk[grp][gt * 8 + 2 * j + 1] = fk.y;
            sv[grp][gt * 8 + 2 * j] = fv.x; sv[grp][gt * 8 + 2 * j + 1] = fv.y;
        }
    }
    __syncthreads();

    const int warp = gt >> 5, lane = gt & 31;
#pragma unroll
    for (int p = warp * 4; p < warp * 4 + 4; p++) {
        int h = p >> 2, g = p & 3;
        float s = 0.f;
#pragma unroll
        for (int e = lane; e < HD; e += 32) s += sq[grp][h * HD + e] * sk[grp][g * HD + e];
#pragma unroll
        for (int off = 16; off; off >>= 1) s += __shfl_xor_sync(0xffffffffu, s, off);
        if (lane == 0) sw[grp][h][g] = s * 0.0625f;
    }
    __syncthreads();

    if (gt < NH) {
        float s0 = sw[grp][gt][0], s1 = sw[grp][gt][1], s2 = sw[grp][gt][2], s3 = sw[grp][gt][3];
        float m = fmaxf(fmaxf(s0, s1), fmaxf(s2, s3));
        float e0 = __expf(s0 - m), e1 = __expf(s1 - m), e2 = __expf(s2 - m), e3 = __expf(s3 - m);
        float inv = 1.f / (e0 + e1 + e2 + e3);
        sw[grp][gt][0] = e0 * inv; sw[grp][gt][1] = e1 * inv;
        sw[grp][gt][2] = e2 * inv; sw[grp][gt][3] = e3 * inv;
    }
    __syncthreads();

    size_t base = (size_t)node * DIM;
#pragma unroll
    for (int idx = gt; idx < DIM; idx += 128) {
        int h = idx >> 8, d = idx & 255;
        float s = sw[grp][h][0] * sv[grp][d] + sw[grp][h][1] * sv[grp][HD + d] +
                  sw[grp][h][2] * sv[grp][2 * HD + d] + sw[grp][h][3] * sv[grp][3 * HD + d];
        Ah[base + idx] = __float2half_rn(s);
    }
}

// ---------------- launch -----------------------------------------------------
extern "C" void kernel_launch(void* const* d_in, const int* in_sizes, int n_in,
                              void* d_out, int out_size)
{
    const float* x  = (const float*)d_in[0];
    const float* Wq = (const float*)d_in[2];
    const float* bq = (const float*)d_in[3];
    const float* Wk = (const float*)d_in[4];
    const float* bk = (const float*)d_in[5];
    const float* Wv = (const float*)d_in[6];
    const float* bv = (const float*)d_in[7];
    const float* Wo = (const float*)d_in[8];
    const float* bo = (const float*)d_in[9];
    float* out = (float*)d_out;

    __half *xh, *qkv, *ah, *wT;
    float* bqkv;
    cudaGetSymbolAddress((void**)&xh, g_xh);
    cudaGetSymbolAddress((void**)&qkv, g_qkv);
    cudaGetSymbolAddress((void**)&ah, g_ah);
    cudaGetSymbolAddress((void**)&wT, g_wT);
    cudaGetSymbolAddress((void**)&bqkv, g_bqkv);

    cudaFuncSetAttribute(gemm_h<true>,  cudaFuncAttributeMaxDynamicSharedMemorySize, GEMM_SMEM);
    cudaFuncSetAttribute(gemm_h<false>, cudaFuncAttributeMaxDynamicSharedMemorySize, GEMM_SMEM);

    const size_t WSZ = (size_t)DIM * DIM;

    cvt_f2h<<<2048, 256>>>((const float4*)x, (uint2*)xh, M_ROWS * DIM / 4);
    dim3 tgrid(32, 32, 4), tblk(32, 8);
    cvt_wT4<<<tgrid, tblk>>>(Wq, Wk, Wv, Wo, wT);
    concat_bias<<<4, 256>>>(bq, bk, bv, bqkv);

    // Fused QKV GEMM: B = wT rows [0, 3072), C = qkv [M, 3072]
    dim3 gQKV(NQKV / BN, M_ROWS / BM);  // (24, 128)
    gemm_h<true><<<gQKV, 256, GEMM_SMEM>>>(xh, wT, bqkv, qkv, NQKV);

    attn_kernel<<<M_ROWS / 2, 256>>>(qkv, ah);

    dim3 gO(DIM / BN, M_ROWS / BM);     // (8, 128)
    gemm_h<false><<<gO, 256, GEMM_SMEM>>>(ah, wT + 3 * WSZ, bo, out, DIM);
}

// round 11
// speedup vs baseline: 1.1514x; 1.1514x over previous
#include <cuda_runtime.h>
#include <cuda_fp16.h>
#include <cstdint>

#define M_ROWS (8 * 4096)
#define DIM 1024
#define NQKV 3072
#define NH 4
#define HD 256

#define BM 128
#define BK 32
#define STAGES 4
#define KITERS (DIM / BK)                 // 32

// ---------------- scratch (static device arrays; no allocation) -------------
__device__ __half g_xh[(size_t)M_ROWS * DIM];
__device__ __half g_qkv[(size_t)M_ROWS * NQKV];
__device__ __half g_ah[(size_t)M_ROWS * DIM];
__device__ __half g_wT[4][(size_t)DIM * DIM];
__device__ float  g_bqkv[NQKV];

// ---------------- PTX helpers ------------------------------------------------
__device__ __forceinline__ uint32_t smem_u32(const void* p) {
    uint32_t a;
    asm("{ .reg .u64 t; cvta.to.shared.u64 t, %1; cvt.u32.u64 %0, t; }" : "=r"(a) : "l"(p));
    return a;
}
#define CP16(dst, src) \
    asm volatile("cp.async.cg.shared.global [%0], [%1], 16;" :: "r"(dst), "l"(src))
#define CP_COMMIT() asm volatile("cp.async.commit_group;" ::: "memory")
#define CP_WAIT2()  asm volatile("cp.async.wait_group 2;" ::: "memory")

#define LDSM_X4(r, addr) \
    asm volatile("ldmatrix.sync.aligned.m8n8.x4.shared.b16 {%0,%1,%2,%3}, [%4];" \
        : "=r"((r)[0]), "=r"((r)[1]), "=r"((r)[2]), "=r"((r)[3]) : "r"(addr))

#define MMA16816(d, a, b) \
    asm volatile("mma.sync.aligned.m16n8k16.row.col.f32.f16.f16.f32 " \
        "{%0,%1,%2,%3}, {%4,%5,%6,%7}, {%8,%9}, {%0,%1,%2,%3};" \
        : "+f"((d)[0]), "+f"((d)[1]), "+f"((d)[2]), "+f"((d)[3]) \
        : "r"((a)[0]), "r"((a)[1]), "r"((a)[2]), "r"((a)[3]), "r"((b)[0]), "r"((b)[1]))

// ---------------- fp16 GEMM via mma.sync -------------------------------------
// C[M, ldc] = A[M,1024] @ B^T + bias, A fp16 row-major, B stored [N][K] fp16.
// CTA 128 x (2*WN), 4 warps (2 over M x 2 over N), warp tile 64 x WN.
// 128 threads, 2 CTAs/SM (the R10 lesson: barriers must overlap across CTAs).
// WN=96 raises MMA-per-crossbar-byte (82% ceiling vs 68% at WN=64).
template <int WN, bool OUT_HALF>
__global__ void __launch_bounds__(128, 2)
gemm_h(const __half* __restrict__ A, const __half* __restrict__ B,
       const float* __restrict__ bias, void* __restrict__ Cv, int ldc)
{
    constexpr int BNT = 2 * WN;                 // CTA N-tile
    constexpr int NT = WN / 8;                  // MMA n-tiles per warp
    constexpr int NLD = WN / 16;                // B ldsm.x4 per kk per warp
    constexpr int A_BYTES = 128 * 80;
    constexpr int B_BYTES = BNT * 80;
    constexpr int STAGE_BYTES = A_BYTES + B_BYTES;
    constexpr int BCH = BNT / 32;               // B chunks per thread

    extern __shared__ char sm[];
    const uint32_t sbase = smem_u32(sm);

    const int tid = threadIdx.x;
    const int wid = tid >> 5, lane = tid & 31;
    const int warp_m = wid & 1;
    const int warp_n = wid >> 1;
    const int rowBase = blockIdx.y * BM;
    const int colBase = blockIdx.x * BNT;

    const int r0 = tid >> 2, c0 = tid & 3;      // r0 in [0,32)
    const __half* gA = A + (size_t)(rowBase + r0) * DIM + c0 * 8;
    const __half* gB = B + (size_t)(colBase + r0) * DIM + c0 * 8;
    const uint32_t sOff = (uint32_t)(r0 * 80 + c0 * 16);

    float acc[4][NT][4];
#pragma unroll
    for (int i = 0; i < 4; i++)
#pragma unroll
        for (int j = 0; j < NT; j++)
#pragma unroll
            for (int q = 0; q < 4; q++) acc[i][j][q] = 0.f;

    auto prefetch = [&](int s, int k0) {
        uint32_t sA = sbase + s * STAGE_BYTES;
        uint32_t sB = sA + A_BYTES;
        const __half* pa = gA + k0;
        const __half* pb = gB + k0;
#pragma unroll
        for (int j = 0; j < 4; j++)
            CP16(sA + sOff + j * 32 * 80, pa + (size_t)j * 32 * DIM);
#pragma unroll
        for (int j = 0; j < BCH; j++)
            CP16(sB + sOff + j * 32 * 80, pb + (size_t)j * 32 * DIM);
        CP_COMMIT();
    };

#pragma unroll
    for (int s = 0; s < STAGES - 1; s++) prefetch(s, s * BK);

    const uint32_t aLane = (uint32_t)((warp_m * 64 + (lane & 15)) * 80 + (lane >> 4) * 16);
    const uint32_t bLane = (uint32_t)((warp_n * WN + (lane & 7) + ((lane >> 4) << 3)) * 80 +
                                      ((lane >> 3) & 1) * 16);

    for (int i = 0; i < KITERS; i++) {
        CP_WAIT2();
        __syncthreads();
        if (i + STAGES - 1 < KITERS) prefetch((i + STAGES - 1) & (STAGES - 1), (i + STAGES - 1) * BK);
        else CP_COMMIT();

        const uint32_t st = sbase + (i & (STAGES - 1)) * STAGE_BYTES;
        const uint32_t aB = st + aLane;
        const uint32_t bB = st + A_BYTES + bLane;
#pragma unroll
        for (int kk = 0; kk < 2; kk++) {
            uint32_t af[4][4], bf[NLD][4];
#pragma unroll
            for (int mt = 0; mt < 4; mt++) LDSM_X4(af[mt], aB + mt * 16 * 80 + kk * 32);
#pragma unroll
            for (int p = 0; p < NLD; p++) LDSM_X4(bf[p], bB + p * 16 * 80 + kk * 32);
#pragma unroll
            for (int mt = 0; mt < 4; mt++)
#pragma unroll
                for (int nt = 0; nt < NT; nt++)
                    MMA16816(acc[mt][nt], af[mt], bf[nt >> 1] + (nt & 1) * 2);
        }
    }

    // epilogue
#pragma unroll
    for (int mt = 0; mt < 4; mt++) {
        const int row = rowBase + warp_m * 64 + mt * 16 + (lane >> 2);
#pragma unroll
        for (int nt = 0; nt < NT; nt++) {
            const int col = colBase + warp_n * WN + nt * 8 + (lane & 3) * 2;
            const float bx = bias[col], by = bias[col + 1];
            if (OUT_HALF) {
                __half* C = (__half*)Cv;
                *(__half2*)(C + (size_t)row * ldc + col) =
                    __floats2half2_rn(acc[mt][nt][0] + bx, acc[mt][nt][1] + by);
                *(__half2*)(C + (size_t)(row + 8) * ldc + col) =
                    __floats2half2_rn(acc[mt][nt][2] + bx, acc[mt][nt][3] + by);
            } else {
                float* C = (float*)Cv;
                *(float2*)(C + (size_t)row * ldc + col) =
                    make_float2(acc[mt][nt][0] + bx, acc[mt][nt][1] + by);
                *(float2*)(C + (size_t)(row + 8) * ldc + col) =
                    make_float2(acc[mt][nt][2] + bx, acc[mt][nt][3] + by);
            }
        }
    }
}

// ---------------- conversion kernels -----------------------------------------
__global__ void cvt_f2h(const float4* __restrict__ in, uint2* __restrict__ out, int n4)
{
    for (int i = blockIdx.x * blockDim.x + threadIdx.x; i < n4; i += gridDim.x * blockDim.x) {
        float4 v = in[i];
        __half2 h01 = __floats2half2_rn(v.x, v.y);
        __half2 h23 = __floats2half2_rn(v.z, v.w);
        out[i] = make_uint2(*(uint32_t*)&h01, *(uint32_t*)&h23);
    }
}

// 4 weights: W[K][N] f32 -> WT[N][K] fp16
__global__ void cvt_wT4(const float* __restrict__ W0, const float* __restrict__ W1,
                        const float* __restrict__ W2, const float* __restrict__ W3,
                        __half* __restrict__ T)
{
    __shared__ float tile[32][33];
    const float* W = (blockIdx.z == 0) ? W0 : (blockIdx.z == 1) ? W1 : (blockIdx.z == 2) ? W2 : W3;
    __half* Tz = T + (size_t)blockIdx.z * DIM * DIM;
    int n0 = blockIdx.x * 32, k0 = blockIdx.y * 32;
    int tx = threadIdx.x, ty = threadIdx.y;
#pragma unroll
    for (int j = 0; j < 32; j += 8)
        tile[ty + j][tx] = W[(size_t)(k0 + ty + j) * DIM + n0 + tx];
    __syncthreads();
#pragma unroll
    for (int j = 0; j < 32; j += 8)
        Tz[(size_t)(n0 + ty + j) * DIM + k0 + tx] = __float2half_rn(tile[tx][ty + j]);
}

__global__ void concat_bias(const float* __restrict__ bq, const float* __restrict__ bk,
                            const float* __restrict__ bv, float* __restrict__ o)
{
    int i = blockIdx.x * blockDim.x + threadIdx.x;
    if (i < DIM) {
        o[i] = bq[i];
        o[i + DIM] = bk[i];
        o[i + 2 * DIM] = bv[i];
    }
}

// ---------------- per-node head-head attention: 2 nodes per 256-thr block ----
__global__ __launch_bounds__(256)
void attn_kernel(const __half* __restrict__ QKV, __half* __restrict__ Ah)
{
    __shared__ float sq[2][DIM], sk[2][DIM], sv[2][DIM];
    __shared__ float sw[2][NH][NH];

    const int tid = threadIdx.x;
    const int grp = tid >> 7;
    const int gt = tid & 127;
    const int node = blockIdx.x * 2 + grp;

    const __half* q = QKV + (size_t)node * NQKV;
    const __half* k = q + DIM;
    const __half* v = q + 2 * DIM;

    {
        uint4 vq = ((const uint4*)q)[gt];
        uint4 vk = ((const uint4*)k)[gt];
        uint4 vv = ((const uint4*)v)[gt];
        const __half2* hq = (const __half2*)&vq;
        const __half2* hk = (const __half2*)&vk;
        const __half2* hv = (const __half2*)&vv;
#pragma unroll
        for (int j = 0; j < 4; j++) {
            float2 fq = __half22float2(hq[j]);
            float2 fk = __half22float2(hk[j]);
            float2 fv = __half22float2(hv[j]);
            sq[grp][gt * 8 + 2 * j] = fq.x; sq[grp][gt * 8 + 2 * j + 1] = fq.y;
            sk[grp][gt * 8 + 2 * j] = fk.x; sk[grp][gt * 8 + 2 * j + 1] = fk.y;
            sv[grp][gt * 8 + 2 * j] = fv.x; sv[grp][gt * 8 + 2 * j + 1] = fv.y;
        }
    }
    __syncthreads();

    const int warp = gt >> 5, lane = gt & 31;
#pragma unroll
    for (int p = warp * 4; p < warp * 4 + 4; p++) {
        int h = p >> 2, g = p & 3;
        float s = 0.f;
#pragma unroll
        for (int e = lane; e < HD; e += 32) s += sq[grp][h * HD + e] * sk[grp][g * HD + e];
#pragma unroll
        for (int off = 16; off; off >>= 1) s += __shfl_xor_sync(0xffffffffu, s, off);
        if (lane == 0) sw[grp][h][g] = s * 0.0625f;
    }
    __syncthreads();

    if (gt < NH) {
        float s0 = sw[grp][gt][0], s1 = sw[grp][gt][1], s2 = sw[grp][gt][2], s3 = sw[grp][gt][3];
        float m = fmaxf(fmaxf(s0, s1), fmaxf(s2, s3));
        float e0 = __expf(s0 - m), e1 = __expf(s1 - m), e2 = __expf(s2 - m), e3 = __expf(s3 - m);
        float inv = 1.f / (e0 + e1 + e2 + e3);
        sw[grp][gt][0] = e0 * inv; sw[grp][gt][1] = e1 * inv;
        sw[grp][gt][2] = e2 * inv; sw[grp][gt][3] = e3 * inv;
    }
    __syncthreads();

    size_t base = (size_t)node * DIM;
#pragma unroll
    for (int idx = gt; idx < DIM; idx += 128) {
        int h = idx >> 8, d = idx & 255;
        float s = sw[grp][h][0] * sv[grp][d] + sw[grp][h][1] * sv[grp][HD + d] +
                  sw[grp][h][2] * sv[grp][2 * HD + d] + sw[grp][h][3] * sv[grp][3 * HD + d];
        Ah[base + idx] = __float2half_rn(s);
    }
}

// ---------------- launch -----------------------------------------------------
extern "C" void kernel_launch(void* const* d_in, const int* in_sizes, int n_in,
                              void* d_out, int out_size)
{
    const float* x  = (const float*)d_in[0];
    const float* Wq = (const float*)d_in[2];
    const float* bq = (const float*)d_in[3];
    const float* Wk = (const float*)d_in[4];
    const float* bk = (const float*)d_in[5];
    const float* Wv = (const float*)d_in[6];
    const float* bv = (const float*)d_in[7];
    const float* Wo = (const float*)d_in[8];
    const float* bo = (const float*)d_in[9];
    float* out = (float*)d_out;

    __half *xh, *qkv, *ah, *wT;
    float* bqkv;
    cudaGetSymbolAddress((void**)&xh, g_xh);
    cudaGetSymbolAddress((void**)&qkv, g_qkv);
    cudaGetSymbolAddress((void**)&ah, g_ah);
    cudaGetSymbolAddress((void**)&wT, g_wT);
    cudaGetSymbolAddress((void**)&bqkv, g_bqkv);

    // QKV: 128x192 tile (WN=96); O: 128x128 tile (WN=64)
    const int SMEM_QKV = STAGES * (128 * 80 + 192 * 80);  // 102400
    const int SMEM_O   = STAGES * (128 * 80 + 128 * 80);  // 81920
    cudaFuncSetAttribute(gemm_h<96, true>,  cudaFuncAttributeMaxDynamicSharedMemorySize, SMEM_QKV);
    cudaFuncSetAttribute(gemm_h<64, false>, cudaFuncAttributeMaxDynamicSharedMemorySize, SMEM_O);

    const size_t WSZ = (size_t)DIM * DIM;

    cvt_f2h<<<2048, 256>>>((const float4*)x, (uint2*)xh, M_ROWS * DIM / 4);
    dim3 tgrid(32, 32, 4), tblk(32, 8);
    cvt_wT4<<<tgrid, tblk>>>(Wq, Wk, Wv, Wo, wT);
    concat_bias<<<4, 256>>>(bq, bk, bv, bqkv);

    // Fused QKV GEMM: B = wT rows [0, 3072), C = qkv [M, 3072]
    dim3 gQKV(NQKV / 192, M_ROWS / BM);  // (16, 256)
    gemm_h<96, true><<<gQKV, 128, SMEM_QKV>>>(xh, wT, bqkv, qkv, NQKV);

    attn_kernel<<<M_ROWS / 2, 256>>>(qkv, ah);

    dim3 gO(DIM / 128, M_ROWS / BM);     // (8, 256)
    gemm_h<64, false><<<gO, 128, SMEM_O>>>(ah, wT + 3 * WSZ, bo, out, DIM);
}

// round 13
// speedup vs baseline: 1.2381x; 1.0753x over previous
#include <cuda_runtime.h>
#include <cuda_fp16.h>
#include <cstdint>

#define M_ROWS (8 * 4096)
#define DIM 1024
#define NQKV 3072
#define NH 4
#define HD 256

#define BM 128
#define BN 128
#define BK 32
#define STAGES 5
#define KITERS (DIM / BK)                 // 32
#define A_BYTES (128 * 80)                // 10240
#define B_BYTES (128 * 80)                // 10240
#define STAGE_BYTES (A_BYTES + B_BYTES)   // 20480
#define GEMM_SMEM (STAGES * STAGE_BYTES)  // 102400

// ---------------- scratch (static device arrays; no allocation) -------------
__device__ __half g_xh[(size_t)M_ROWS * DIM];
__device__ __half g_qkv[(size_t)M_ROWS * NQKV];
__device__ __half g_ah[(size_t)M_ROWS * DIM];
__device__ __half g_wT[4][(size_t)DIM * DIM];
__device__ float  g_bqkv[NQKV];

// ---------------- PTX helpers ------------------------------------------------
__device__ __forceinline__ uint32_t smem_u32(const void* p) {
    uint32_t a;
    asm("{ .reg .u64 t; cvta.to.shared.u64 t, %1; cvt.u32.u64 %0, t; }" : "=r"(a) : "l"(p));
    return a;
}
#define CP16(dst, src) \
    asm volatile("cp.async.cg.shared.global [%0], [%1], 16;" :: "r"(dst), "l"(src))
#define CP_COMMIT() asm volatile("cp.async.commit_group;" ::: "memory")
#define CP_WAIT3()  asm volatile("cp.async.wait_group 3;" ::: "memory")

#define LDSM_X4(r, addr) \
    asm volatile("ldmatrix.sync.aligned.m8n8.x4.shared.b16 {%0,%1,%2,%3}, [%4];" \
        : "=r"((r)[0]), "=r"((r)[1]), "=r"((r)[2]), "=r"((r)[3]) : "r"(addr))

#define MMA16816(d, a, b) \
    asm volatile("mma.sync.aligned.m16n8k16.row.col.f32.f16.f16.f32 " \
        "{%0,%1,%2,%3}, {%4,%5,%6,%7}, {%8,%9}, {%0,%1,%2,%3};" \
        : "+f"((d)[0]), "+f"((d)[1]), "+f"((d)[2]), "+f"((d)[3]) \
        : "r"((a)[0]), "r"((a)[1]), "r"((a)[2]), "r"((a)[3]), "r"((b)[0]), "r"((b)[1]))

// ---------------- fp16 GEMM via mma.sync (R9 shape + 5-stage pipeline) -------
// C[M, ldc] = A[M,1024] @ B^T + bias, A fp16 row-major, B stored [N][K] fp16.
// CTA 128x128, 4 warps (2x2), warp tile 64x64. 128 threads, 2 CTAs/SM.
// STAGES=5 with wait_group 3: one extra stage of LSU slack per barrier.
template <bool OUT_HALF>
__global__ void __launch_bounds__(128, 2)
gemm_h(const __half* __restrict__ A, const __half* __restrict__ B,
       const float* __restrict__ bias, void* __restrict__ Cv, int ldc)
{
    extern __shared__ char sm[];
    const uint32_t sbase = smem_u32(sm);

    const int tid = threadIdx.x;
    const int wid = tid >> 5, lane = tid & 31;
    const int warp_m = wid & 1;
    const int warp_n = wid >> 1;
    const int rowBase = blockIdx.y * BM;
    const int colBase = blockIdx.x * BN;

    const int r0 = tid >> 2, c0 = tid & 3;
    const __half* gA = A + (size_t)(rowBase + r0) * DIM + c0 * 8;
    const __half* gB = B + (size_t)(colBase + r0) * DIM + c0 * 8;
    const uint32_t sOff = (uint32_t)(r0 * 80 + c0 * 16);

    float acc[4][8][4];
#pragma unroll
    for (int i = 0; i < 4; i++)
#pragma unroll
        for (int j = 0; j < 8; j++)
#pragma unroll
            for (int q = 0; q < 4; q++) acc[i][j][q] = 0.f;

    auto prefetch = [&](int s, int k0) {
        uint32_t sA = sbase + s * STAGE_BYTES;
        uint32_t sB = sA + A_BYTES;
        const __half* pa = gA + k0;
        const __half* pb = gB + k0;
#pragma unroll
        for (int j = 0; j < 4; j++) {
            CP16(sA + sOff + j * 32 * 80, pa + (size_t)j * 32 * DIM);
            CP16(sB + sOff + j * 32 * 80, pb + (size_t)j * 32 * DIM);
        }
        CP_COMMIT();
    };

#pragma unroll
    for (int s = 0; s < STAGES - 1; s++) prefetch(s, s * BK);

    const uint32_t aLane = (uint32_t)((warp_m * 64 + (lane & 15)) * 80 + (lane >> 4) * 16);
    const uint32_t bLane = (uint32_t)((warp_n * 64 + (lane & 7) + ((lane >> 4) << 3)) * 80 +
                                      ((lane >> 3) & 1) * 16);

    int stage = 0, pstage = STAGES - 1;
    for (int i = 0; i < KITERS; i++) {
        CP_WAIT3();
        __syncthreads();
        if (i + STAGES - 1 < KITERS) {
            prefetch(pstage, (i + STAGES - 1) * BK);
            if (++pstage == STAGES) pstage = 0;
        } else {
            CP_COMMIT();
        }

        const uint32_t st = sbase + stage * STAGE_BYTES;
        if (++stage == STAGES) stage = 0;
        const uint32_t aB = st + aLane;
        const uint32_t bB = st + A_BYTES + bLane;
#pragma unroll
        for (int kk = 0; kk < 2; kk++) {
            uint32_t af[4][4], bf[4][4];
#pragma unroll
            for (int mt = 0; mt < 4; mt++) LDSM_X4(af[mt], aB + mt * 16 * 80 + kk * 32);
#pragma unroll
            for (int p = 0; p < 4; p++)  LDSM_X4(bf[p], bB + p * 16 * 80 + kk * 32);
#pragma unroll
            for (int mt = 0; mt < 4; mt++)
#pragma unroll
                for (int nt = 0; nt < 8; nt++)
                    MMA16816(acc[mt][nt], af[mt], bf[nt >> 1] + (nt & 1) * 2);
        }
    }

    // epilogue
#pragma unroll
    for (int mt = 0; mt < 4; mt++) {
        const int row = rowBase + warp_m * 64 + mt * 16 + (lane >> 2);
#pragma unroll
        for (int nt = 0; nt < 8; nt++) {
            const int col = colBase + warp_n * 64 + nt * 8 + (lane & 3) * 2;
            const float bx = bias[col], by = bias[col + 1];
            if (OUT_HALF) {
                __half* C = (__half*)Cv;
                *(__half2*)(C + (size_t)row * ldc + col) =
                    __floats2half2_rn(acc[mt][nt][0] + bx, acc[mt][nt][1] + by);
                *(__half2*)(C + (size_t)(row + 8) * ldc + col) =
                    __floats2half2_rn(acc[mt][nt][2] + bx, acc[mt][nt][3] + by);
            } else {
                float* C = (float*)Cv;
                *(float2*)(C + (size_t)row * ldc + col) =
                    make_float2(acc[mt][nt][0] + bx, acc[mt][nt][1] + by);
                *(float2*)(C + (size_t)(row + 8) * ldc + col) =
                    make_float2(acc[mt][nt][2] + bx, acc[mt][nt][3] + by);
            }
        }
    }
}

// ---------------- conversion kernels -----------------------------------------
__global__ void cvt_f2h(const float4* __restrict__ in, uint2* __restrict__ out, int n4)
{
    for (int i = blockIdx.x * blockDim.x + threadIdx.x; i < n4; i += gridDim.x * blockDim.x) {
        float4 v = in[i];
        __half2 h01 = __floats2half2_rn(v.x, v.y);
        __half2 h23 = __floats2half2_rn(v.z, v.w);
        out[i] = make_uint2(*(uint32_t*)&h01, *(uint32_t*)&h23);
    }
}

// 4 weights: W[K][N] f32 -> WT[N][K] fp16
__global__ void cvt_wT4(const float* __restrict__ W0, const float* __restrict__ W1,
                        const float* __restrict__ W2, const float* __restrict__ W3,
                        __half* __restrict__ T)
{
    __shared__ float tile[32][33];
    const float* W = (blockIdx.z == 0) ? W0 : (blockIdx.z == 1) ? W1 : (blockIdx.z == 2) ? W2 : W3;
    __half* Tz = T + (size_t)blockIdx.z * DIM * DIM;
    int n0 = blockIdx.x * 32, k0 = blockIdx.y * 32;
    int tx = threadIdx.x, ty = threadIdx.y;
#pragma unroll
    for (int j = 0; j < 32; j += 8)
        tile[ty + j][tx] = W[(size_t)(k0 + ty + j) * DIM + n0 + tx];
    __syncthreads();
#pragma unroll
    for (int j = 0; j < 32; j += 8)
        Tz[(size_t)(n0 + ty + j) * DIM + k0 + tx] = __float2half_rn(tile[tx][ty + j]);
}

__global__ void concat_bias(const float* __restrict__ bq, const float* __restrict__ bk,
                            const float* __restrict__ bv, float* __restrict__ o)
{
    int i = blockIdx.x * blockDim.x + threadIdx.x;
    if (i < DIM) {
        o[i] = bq[i];
        o[i + DIM] = bk[i];
        o[i + 2 * DIM] = bv[i];
    }
}

// ---------------- per-node head-head attention: 2 nodes per 256-thr block ----
__global__ __launch_bounds__(256)
void attn_kernel(const __half* __restrict__ QKV, __half* __restrict__ Ah)
{
    __shared__ float sq[2][DIM], sk[2][DIM], sv[2][DIM];
    __shared__ float sw[2][NH][NH];

    const int tid = threadIdx.x;
    const int grp = tid >> 7;
    const int gt = tid & 127;
    const int node = blockIdx.x * 2 + grp;

    const __half* q = QKV + (size_t)node * NQKV;
    const __half* k = q + DIM;
    const __half* v = q + 2 * DIM;

    {
        uint4 vq = ((const uint4*)q)[gt];
        uint4 vk = ((const uint4*)k)[gt];
        uint4 vv = ((const uint4*)v)[gt];
        const __half2* hq = (const __half2*)&vq;
        const __half2* hk = (const __half2*)&vk;
        const __half2* hv = (const __half2*)&vv;
#pragma unroll
        for (int j = 0; j < 4; j++) {
            float2 fq = __half22float2(hq[j]);
            float2 fk = __half22float2(hk[j]);
            float2 fv = __half22float2(hv[j]);
            sq[grp][gt * 8 + 2 * j] = fq.x; sq[grp][gt * 8 + 2 * j + 1] = fq.y;
            sk[grp][gt * 8 + 2 * j] = fk.x; sk[grp][gt * 8 + 2 * j + 1] = fk.y;
            sv[grp][gt * 8 + 2 * j] = fv.x; sv[grp][gt * 8 + 2 * j + 1] = fv.y;
        }
    }
    __syncthreads();

    const int warp = gt >> 5, lane = gt & 31;
#pragma unroll
    for (int p = warp * 4; p < warp * 4 + 4; p++) {
        int h = p >> 2, g = p & 3;
        float s = 0.f;
#pragma unroll
        for (int e = lane; e < HD; e += 32) s += sq[grp][h * HD + e] * sk[grp][g * HD + e];
#pragma unroll
        for (int off = 16; off; off >>= 1) s += __shfl_xor_sync(0xffffffffu, s, off);
        if (lane == 0) sw[grp][h][g] = s * 0.0625f;
    }
    __syncthreads();

    if (gt < NH) {
        float s0 = sw[grp][gt][0], s1 = sw[grp][gt][1], s2 = sw[grp][gt][2], s3 = sw[grp][gt][3];
        float m = fmaxf(fmaxf(s0, s1), fmaxf(s2, s3));
        float e0 = __expf(s0 - m), e1 = __expf(s1 - m), e2 = __expf(s2 - m), e3 = __expf(s3 - m);
        float inv = 1.f / (e0 + e1 + e2 + e3);
        sw[grp][gt][0] = e0 * inv; sw[grp][gt][1] = e1 * inv;
        sw[grp][gt][2] = e2 * inv; sw[grp][gt][3] = e3 * inv;
    }
    __syncthreads();

    size_t base = (size_t)node * DIM;
#pragma unroll
    for (int idx = gt; idx < DIM; idx += 128) {
        int h = idx >> 8, d = idx & 255;
        float s = sw[grp][h][0] * sv[grp][d] + sw[grp][h][1] * sv[grp][HD + d] +
                  sw[grp][h][2] * sv[grp][2 * HD + d] + sw[grp][h][3] * sv[grp][3 * HD + d];
        Ah[base + idx] = __float2half_rn(s);
    }
}

// ---------------- launch -----------------------------------------------------
extern "C" void kernel_launch(void* const* d_in, const int* in_sizes, int n_in,
                              void* d_out, int out_size)
{
    const float* x  = (const float*)d_in[0];
    const float* Wq = (const float*)d_in[2];
    const float* bq = (const float*)d_in[3];
    const float* Wk = (const float*)d_in[4];
    const float* bk = (const float*)d_in[5];
    const float* Wv = (const float*)d_in[6];
    const float* bv = (const float*)d_in[7];
    const float* Wo = (const float*)d_in[8];
    const float* bo = (const float*)d_in[9];
    float* out = (float*)d_out;

    __half *xh, *qkv, *ah, *wT;
    float* bqkv;
    cudaGetSymbolAddress((void**)&xh, g_xh);
    cudaGetSymbolAddress((void**)&qkv, g_qkv);
    cudaGetSymbolAddress((void**)&ah, g_ah);
    cudaGetSymbolAddress((void**)&wT, g_wT);
    cudaGetSymbolAddress((void**)&bqkv, g_bqkv);

    cudaFuncSetAttribute(gemm_h<true>,  cudaFuncAttributeMaxDynamicSharedMemorySize, GEMM_SMEM);
    cudaFuncSetAttribute(gemm_h<false>, cudaFuncAttributeMaxDynamicSharedMemorySize, GEMM_SMEM);

    const size_t WSZ = (size_t)DIM * DIM;

    cvt_f2h<<<2048, 256>>>((const float4*)x, (uint2*)xh, M_ROWS * DIM / 4);
    dim3 tgrid(32, 32, 4), tblk(32, 8);
    cvt_wT4<<<tgrid, tblk>>>(Wq, Wk, Wv, Wo, wT);
    concat_bias<<<4, 256>>>(bq, bk, bv, bqkv);

    // Fused QKV GEMM: B = wT rows [0, 3072), C = qkv [M, 3072]
    dim3 gQKV(NQKV / BN, M_ROWS / BM);  // (24, 256)
    gemm_h<true><<<gQKV, 128, GEMM_SMEM>>>(xh, wT, bqkv, qkv, NQKV);

    attn_kernel<<<M_ROWS / 2, 256>>>(qkv, ah);

    dim3 gO(DIM / BN, M_ROWS / BM);     // (8, 256)
    gemm_h<false><<<gO, 128, GEMM_SMEM>>>(ah, wT + 3 * WSZ, bo, out, DIM);
}

// round 14
// speedup vs baseline: 1.2530x; 1.0121x over previous
#include <cuda_runtime.h>
#include <cuda_fp16.h>
#include <cstdint>

#define M_ROWS (8 * 4096)
#define DIM 1024
#define NQKV 3072
#define NH 4
#define HD 256

#define BM 128
#define BN 128
#define BK 32
#define STAGES 4
#define KITERS (DIM / BK)                 // 32
#define A_BYTES (128 * 80)                // 10240
#define B_BYTES (128 * 80)                // 10240
#define STAGE_BYTES (A_BYTES + B_BYTES)   // 20480
#define GEMM_SMEM (STAGES * STAGE_BYTES)  // 81920

// ---------------- scratch (static device arrays; no allocation) -------------
__device__ __half g_xh[(size_t)M_ROWS * DIM];
__device__ __half g_qkv[(size_t)M_ROWS * NQKV];
__device__ __half g_ah[(size_t)M_ROWS * DIM];
__device__ __half g_wT[4][(size_t)DIM * DIM];
__device__ float  g_bqkv[NQKV];

// ---------------- PTX helpers ------------------------------------------------
__device__ __forceinline__ uint32_t smem_u32(const void* p) {
    uint32_t a;
    asm("{ .reg .u64 t; cvta.to.shared.u64 t, %1; cvt.u32.u64 %0, t; }" : "=r"(a) : "l"(p));
    return a;
}
#define CP16(dst, src) \
    asm volatile("cp.async.cg.shared.global [%0], [%1], 16;" :: "r"(dst), "l"(src))
#define CP_COMMIT() asm volatile("cp.async.commit_group;" ::: "memory")
#define CP_WAIT2()  asm volatile("cp.async.wait_group 2;" ::: "memory")

#define LDSM_X4(r, addr) \
    asm volatile("ldmatrix.sync.aligned.m8n8.x4.shared.b16 {%0,%1,%2,%3}, [%4];" \
        : "=r"((r)[0]), "=r"((r)[1]), "=r"((r)[2]), "=r"((r)[3]) : "r"(addr))

#define MMA16816(d, a, b) \
    asm volatile("mma.sync.aligned.m16n8k16.row.col.f32.f16.f16.f32 " \
        "{%0,%1,%2,%3}, {%4,%5,%6,%7}, {%8,%9}, {%0,%1,%2,%3};" \
        : "+f"((d)[0]), "+f"((d)[1]), "+f"((d)[2]), "+f"((d)[3]) \
        : "r"((a)[0]), "r"((a)[1]), "r"((a)[2]), "r"((a)[3]), "r"((b)[0]), "r"((b)[1]))

// ---------------- fp16 GEMM via mma.sync (R9 config — measured optimum) ------
// C[M, ldc] = A[M,1024] @ B^T + bias, A fp16 row-major, B stored [N][K] fp16.
// CTA 128x128, 4 warps (2x2), warp tile 64x64. 128 threads, 2 CTAs/SM.
template <bool OUT_HALF>
__global__ void __launch_bounds__(128, 2)
gemm_h(const __half* __restrict__ A, const __half* __restrict__ B,
       const float* __restrict__ bias, void* __restrict__ Cv, int ldc)
{
    extern __shared__ char sm[];
    const uint32_t sbase = smem_u32(sm);

    const int tid = threadIdx.x;
    const int wid = tid >> 5, lane = tid & 31;
    const int warp_m = wid & 1;
    const int warp_n = wid >> 1;
    const int rowBase = blockIdx.y * BM;
    const int colBase = blockIdx.x * BN;

    const int r0 = tid >> 2, c0 = tid & 3;
    const __half* gA = A + (size_t)(rowBase + r0) * DIM + c0 * 8;
    const __half* gB = B + (size_t)(colBase + r0) * DIM + c0 * 8;
    const uint32_t sOff = (uint32_t)(r0 * 80 + c0 * 16);

    float acc[4][8][4];
#pragma unroll
    for (int i = 0; i < 4; i++)
#pragma unroll
        for (int j = 0; j < 8; j++)
#pragma unroll
            for (int q = 0; q < 4; q++) acc[i][j][q] = 0.f;

    auto prefetch = [&](int s, int k0) {
        uint32_t sA = sbase + s * STAGE_BYTES;
        uint32_t sB = sA + A_BYTES;
        const __half* pa = gA + k0;
        const __half* pb = gB + k0;
#pragma unroll
        for (int j = 0; j < 4; j++) {
            CP16(sA + sOff + j * 32 * 80, pa + (size_t)j * 32 * DIM);
            CP16(sB + sOff + j * 32 * 80, pb + (size_t)j * 32 * DIM);
        }
        CP_COMMIT();
    };

#pragma unroll
    for (int s = 0; s < STAGES - 1; s++) prefetch(s, s * BK);

    const uint32_t aLane = (uint32_t)((warp_m * 64 + (lane & 15)) * 80 + (lane >> 4) * 16);
    const uint32_t bLane = (uint32_t)((warp_n * 64 + (lane & 7) + ((lane >> 4) << 3)) * 80 +
                                      ((lane >> 3) & 1) * 16);

    for (int i = 0; i < KITERS; i++) {
        CP_WAIT2();
        __syncthreads();
        if (i + STAGES - 1 < KITERS) prefetch((i + STAGES - 1) & (STAGES - 1), (i + STAGES - 1) * BK);
        else CP_COMMIT();

        const uint32_t st = sbase + (i & (STAGES - 1)) * STAGE_BYTES;
        const uint32_t aB = st + aLane;
        const uint32_t bB = st + A_BYTES + bLane;
#pragma unroll
        for (int kk = 0; kk < 2; kk++) {
            uint32_t af[4][4], bf[4][4];
#pragma unroll
            for (int mt = 0; mt < 4; mt++) LDSM_X4(af[mt], aB + mt * 16 * 80 + kk * 32);
#pragma unroll
            for (int p = 0; p < 4; p++)  LDSM_X4(bf[p], bB + p * 16 * 80 + kk * 32);
#pragma unroll
            for (int mt = 0; mt < 4; mt++)
#pragma unroll
                for (int nt = 0; nt < 8; nt++)
                    MMA16816(acc[mt][nt], af[mt], bf[nt >> 1] + (nt & 1) * 2);
        }
    }

    // epilogue
#pragma unroll
    for (int mt = 0; mt < 4; mt++) {
        const int row = rowBase + warp_m * 64 + mt * 16 + (lane >> 2);
#pragma unroll
        for (int nt = 0; nt < 8; nt++) {
            const int col = colBase + warp_n * 64 + nt * 8 + (lane & 3) * 2;
            const float bx = bias[col], by = bias[col + 1];
            if (OUT_HALF) {
                __half* C = (__half*)Cv;
                *(__half2*)(C + (size_t)row * ldc + col) =
                    __floats2half2_rn(acc[mt][nt][0] + bx, acc[mt][nt][1] + by);
                *(__half2*)(C + (size_t)(row + 8) * ldc + col) =
                    __floats2half2_rn(acc[mt][nt][2] + bx, acc[mt][nt][3] + by);
            } else {
                float* C = (float*)Cv;
                *(float2*)(C + (size_t)row * ldc + col) =
                    make_float2(acc[mt][nt][0] + bx, acc[mt][nt][1] + by);
                *(float2*)(C + (size_t)(row + 8) * ldc + col) =
                    make_float2(acc[mt][nt][2] + bx, acc[mt][nt][3] + by);
            }
        }
    }
}

// ---------------- conversion kernels -----------------------------------------
// x f32 -> fp16, with the QKV bias concat folded into the last block.
__global__ void cvt_f2h_bias(const float4* __restrict__ in, uint2* __restrict__ out, int n4,
                             const float* __restrict__ bq, const float* __restrict__ bk,
                             const float* __restrict__ bv, float* __restrict__ bo_cat)
{
    if (blockIdx.x == gridDim.x - 1) {
        for (int i = threadIdx.x; i < DIM; i += blockDim.x) {
            bo_cat[i] = bq[i];
            bo_cat[i + DIM] = bk[i];
            bo_cat[i + 2 * DIM] = bv[i];
        }
        return;
    }
    const int nb = gridDim.x - 1;
    for (int i = blockIdx.x * blockDim.x + threadIdx.x; i < n4; i += nb * blockDim.x) {
        float4 v = in[i];
        __half2 h01 = __floats2half2_rn(v.x, v.y);
        __half2 h23 = __floats2half2_rn(v.z, v.w);
        out[i] = make_uint2(*(uint32_t*)&h01, *(uint32_t*)&h23);
    }
}

// 4 weights: W[K][N] f32 -> WT[N][K] fp16
__global__ void cvt_wT4(const float* __restrict__ W0, const float* __restrict__ W1,
                        const float* __restrict__ W2, const float* __restrict__ W3,
                        __half* __restrict__ T)
{
    __shared__ float tile[32][33];
    const float* W = (blockIdx.z == 0) ? W0 : (blockIdx.z == 1) ? W1 : (blockIdx.z == 2) ? W2 : W3;
    __half* Tz = T + (size_t)blockIdx.z * DIM * DIM;
    int n0 = blockIdx.x * 32, k0 = blockIdx.y * 32;
    int tx = threadIdx.x, ty = threadIdx.y;
#pragma unroll
    for (int j = 0; j < 32; j += 8)
        tile[ty + j][tx] = W[(size_t)(k0 + ty + j) * DIM + n0 + tx];
    __syncthreads();
#pragma unroll
    for (int j = 0; j < 32; j += 8)
        Tz[(size_t)(n0 + ty + j) * DIM + k0 + tx] = __float2half_rn(tile[tx][ty + j]);
}

// ---------------- per-node head-head attention: 2 nodes per 256-thr block ----
__global__ __launch_bounds__(256)
void attn_kernel(const __half* __restrict__ QKV, __half* __restrict__ Ah)
{
    __shared__ float sq[2][DIM], sk[2][DIM], sv[2][DIM];
    __shared__ float sw[2][NH][NH];

    const int tid = threadIdx.x;
    const int grp = tid >> 7;
    const int gt = tid & 127;
    const int node = blockIdx.x * 2 + grp;

    const __half* q = QKV + (size_t)node * NQKV;
    const __half* k = q + DIM;
    const __half* v = q + 2 * DIM;

    {
        uint4 vq = ((const uint4*)q)[gt];
        uint4 vk = ((const uint4*)k)[gt];
        uint4 vv = ((const uint4*)v)[gt];
        const __half2* hq = (const __half2*)&vq;
        const __half2* hk = (const __half2*)&vk;
        const __half2* hv = (const __half2*)&vv;
#pragma unroll
        for (int j = 0; j < 4; j++) {
            float2 fq = __half22float2(hq[j]);
            float2 fk = __half22float2(hk[j]);
            float2 fv = __half22float2(hv[j]);
            sq[grp][gt * 8 + 2 * j] = fq.x; sq[grp][gt * 8 + 2 * j + 1] = fq.y;
            sk[grp][gt * 8 + 2 * j] = fk.x; sk[grp][gt * 8 + 2 * j + 1] = fk.y;
            sv[grp][gt * 8 + 2 * j] = fv.x; sv[grp][gt * 8 + 2 * j + 1] = fv.y;
        }
    }
    __syncthreads();

    const int warp = gt >> 5, lane = gt & 31;
#pragma unroll
    for (int p = warp * 4; p < warp * 4 + 4; p++) {
        int h = p >> 2, g = p & 3;
        float s = 0.f;
#pragma unroll
        for (int e = lane; e < HD; e += 32) s += sq[grp][h * HD + e] * sk[grp][g * HD + e];
#pragma unroll
        for (int off = 16; off; off >>= 1) s += __shfl_xor_sync(0xffffffffu, s, off);
        if (lane == 0) sw[grp][h][g] = s * 0.0625f;
    }
    __syncthreads();

    if (gt < NH) {
        float s0 = sw[grp][gt][0], s1 = sw[grp][gt][1], s2 = sw[grp][gt][2], s3 = sw[grp][gt][3];
        float m = fmaxf(fmaxf(s0, s1), fmaxf(s2, s3));
        float e0 = __expf(s0 - m), e1 = __expf(s1 - m), e2 = __expf(s2 - m), e3 = __expf(s3 - m);
        float inv = 1.f / (e0 + e1 + e2 + e3);
        sw[grp][gt][0] = e0 * inv; sw[grp][gt][1] = e1 * inv;
        sw[grp][gt][2] = e2 * inv; sw[grp][gt][3] = e3 * inv;
    }
    __syncthreads();

    size_t base = (size_t)node * DIM;
#pragma unroll
    for (int idx = gt; idx < DIM; idx += 128) {
        int h = idx >> 8, d = idx & 255;
        float s = sw[grp][h][0] * sv[grp][d] + sw[grp][h][1] * sv[grp][HD + d] +
                  sw[grp][h][2] * sv[grp][2 * HD + d] + sw[grp][h][3] * sv[grp][3 * HD + d];
        Ah[base + idx] = __float2half_rn(s);
    }
}

// ---------------- launch -----------------------------------------------------
extern "C" void kernel_launch(void* const* d_in, const int* in_sizes, int n_in,
                              void* d_out, int out_size)
{
    const float* x  = (const float*)d_in[0];
    const float* Wq = (const float*)d_in[2];
    const float* bq = (const float*)d_in[3];
    const float* Wk = (const float*)d_in[4];
    const float* bk = (const float*)d_in[5];
    const float* Wv = (const float*)d_in[6];
    const float* bv = (const float*)d_in[7];
    const float* Wo = (const float*)d_in[8];
    const float* bo = (const float*)d_in[9];
    float* out = (float*)d_out;

    __half *xh, *qkv, *ah, *wT;
    float* bqkv;
    cudaGetSymbolAddress((void**)&xh, g_xh);
    cudaGetSymbolAddress((void**)&qkv, g_qkv);
    cudaGetSymbolAddress((void**)&ah, g_ah);
    cudaGetSymbolAddress((void**)&wT, g_wT);
    cudaGetSymbolAddress((void**)&bqkv, g_bqkv);

    cudaFuncSetAttribute(gemm_h<true>,  cudaFuncAttributeMaxDynamicSharedMemorySize, GEMM_SMEM);
    cudaFuncSetAttribute(gemm_h<false>, cudaFuncAttributeMaxDynamicSharedMemorySize, GEMM_SMEM);

    const size_t WSZ = (size_t)DIM * DIM;

    cvt_f2h_bias<<<2049, 256>>>((const float4*)x, (uint2*)xh, M_ROWS * DIM / 4,
                                bq, bk, bv, bqkv);
    dim3 tgrid(32, 32, 4), tblk(32, 8);
    cvt_wT4<<<tgrid, tblk>>>(Wq, Wk, Wv, Wo, wT);

    // Fused QKV GEMM: B = wT rows [0, 3072), C = qkv [M, 3072]
    dim3 gQKV(NQKV / BN, M_ROWS / BM);  // (24, 256)
    gemm_h<true><<<gQKV, 128, GEMM_SMEM>>>(xh, wT, bqkv, qkv, NQKV);

    attn_kernel<<<M_ROWS / 2, 256>>>(qkv, ah);

    dim3 gO(DIM / BN, M_ROWS / BM);     // (8, 256)
    gemm_h<false><<<gO, 128, GEMM_SMEM>>>(ah, wT + 3 * WSZ, bo, out, DIM);
}

// round 15
// speedup vs baseline: 1.3450x; 1.0734x over previous
#include <cuda_runtime.h>
#include <cuda_fp16.h>
#include <cstdint>

#define M_ROWS (8 * 4096)
#define DIM 1024
#define NQKV 3072
#define NH 4
#define HD 256

#define BM 128
#define BN 128
#define BK 32
#define STAGES 4
#define KITERS (DIM / BK)                 // 32
#define A_BYTES (128 * 80)                // 10240
#define B_BYTES (128 * 80)                // 10240
#define STAGE_BYTES (A_BYTES + B_BYTES)   // 20480
#define GEMM_SMEM (STAGES * STAGE_BYTES)  // 81920

// ---------------- scratch (static device arrays; no allocation) -------------
__device__ __half g_xh[(size_t)M_ROWS * DIM];
__device__ __half g_qkv[(size_t)M_ROWS * NQKV];
__device__ __half g_ah[(size_t)M_ROWS * DIM];
__device__ __half g_wT[4][(size_t)DIM * DIM];
__device__ float  g_bqkv[NQKV];

// ---------------- PTX helpers ------------------------------------------------
__device__ __forceinline__ uint32_t smem_u32(const void* p) {
    uint32_t a;
    asm("{ .reg .u64 t; cvta.to.shared.u64 t, %1; cvt.u32.u64 %0, t; }" : "=r"(a) : "l"(p));
    return a;
}
#define CP16(dst, src) \
    asm volatile("cp.async.cg.shared.global [%0], [%1], 16;" :: "r"(dst), "l"(src))
#define CP_COMMIT() asm volatile("cp.async.commit_group;" ::: "memory")
#define CP_WAIT2()  asm volatile("cp.async.wait_group 2;" ::: "memory")

#define LDSM_X4(r, addr) \
    asm volatile("ldmatrix.sync.aligned.m8n8.x4.shared.b16 {%0,%1,%2,%3}, [%4];" \
        : "=r"((r)[0]), "=r"((r)[1]), "=r"((r)[2]), "=r"((r)[3]) : "r"(addr))

#define MMA16816(d, a, b) \
    asm volatile("mma.sync.aligned.m16n8k16.row.col.f32.f16.f16.f32 " \
        "{%0,%1,%2,%3}, {%4,%5,%6,%7}, {%8,%9}, {%0,%1,%2,%3};" \
        : "+f"((d)[0]), "+f"((d)[1]), "+f"((d)[2]), "+f"((d)[3]) \
        : "r"((a)[0]), "r"((a)[1]), "r"((a)[2]), "r"((a)[3]), "r"((b)[0]), "r"((b)[1]))

// ---------------- fp16 GEMM via mma.sync (R9 config — measured optimum) ------
template <bool OUT_HALF>
__global__ void __launch_bounds__(128, 2)
gemm_h(const __half* __restrict__ A, const __half* __restrict__ B,
       const float* __restrict__ bias, void* __restrict__ Cv, int ldc)
{
    extern __shared__ char sm[];
    const uint32_t sbase = smem_u32(sm);

    const int tid = threadIdx.x;
    const int wid = tid >> 5, lane = tid & 31;
    const int warp_m = wid & 1;
    const int warp_n = wid >> 1;
    const int rowBase = blockIdx.y * BM;
    const int colBase = blockIdx.x * BN;

    const int r0 = tid >> 2, c0 = tid & 3;
    const __half* gA = A + (size_t)(rowBase + r0) * DIM + c0 * 8;
    const __half* gB = B + (size_t)(colBase + r0) * DIM + c0 * 8;
    const uint32_t sOff = (uint32_t)(r0 * 80 + c0 * 16);

    float acc[4][8][4];
#pragma unroll
    for (int i = 0; i < 4; i++)
#pragma unroll
        for (int j = 0; j < 8; j++)
#pragma unroll
            for (int q = 0; q < 4; q++) acc[i][j][q] = 0.f;

    auto prefetch = [&](int s, int k0) {
        uint32_t sA = sbase + s * STAGE_BYTES;
        uint32_t sB = sA + A_BYTES;
        const __half* pa = gA + k0;
        const __half* pb = gB + k0;
#pragma unroll
        for (int j = 0; j < 4; j++) {
            CP16(sA + sOff + j * 32 * 80, pa + (size_t)j * 32 * DIM);
            CP16(sB + sOff + j * 32 * 80, pb + (size_t)j * 32 * DIM);
        }
        CP_COMMIT();
    };

#pragma unroll
    for (int s = 0; s < STAGES - 1; s++) prefetch(s, s * BK);

    const uint32_t aLane = (uint32_t)((warp_m * 64 + (lane & 15)) * 80 + (lane >> 4) * 16);
    const uint32_t bLane = (uint32_t)((warp_n * 64 + (lane & 7) + ((lane >> 4) << 3)) * 80 +
                                      ((lane >> 3) & 1) * 16);

    for (int i = 0; i < KITERS; i++) {
        CP_WAIT2();
        __syncthreads();
        if (i + STAGES - 1 < KITERS) prefetch((i + STAGES - 1) & (STAGES - 1), (i + STAGES - 1) * BK);
        else CP_COMMIT();

        const uint32_t st = sbase + (i & (STAGES - 1)) * STAGE_BYTES;
        const uint32_t aB = st + aLane;
        const uint32_t bB = st + A_BYTES + bLane;
#pragma unroll
        for (int kk = 0; kk < 2; kk++) {
            uint32_t af[4][4], bf[4][4];
#pragma unroll
            for (int mt = 0; mt < 4; mt++) LDSM_X4(af[mt], aB + mt * 16 * 80 + kk * 32);
#pragma unroll
            for (int p = 0; p < 4; p++)  LDSM_X4(bf[p], bB + p * 16 * 80 + kk * 32);
#pragma unroll
            for (int mt = 0; mt < 4; mt++)
#pragma unroll
                for (int nt = 0; nt < 8; nt++)
                    MMA16816(acc[mt][nt], af[mt], bf[nt >> 1] + (nt & 1) * 2);
        }
    }

    // epilogue
#pragma unroll
    for (int mt = 0; mt < 4; mt++) {
        const int row = rowBase + warp_m * 64 + mt * 16 + (lane >> 2);
#pragma unroll
        for (int nt = 0; nt < 8; nt++) {
            const int col = colBase + warp_n * 64 + nt * 8 + (lane & 3) * 2;
            const float bx = bias[col], by = bias[col + 1];
            if (OUT_HALF) {
                __half* C = (__half*)Cv;
                *(__half2*)(C + (size_t)row * ldc + col) =
                    __floats2half2_rn(acc[mt][nt][0] + bx, acc[mt][nt][1] + by);
                *(__half2*)(C + (size_t)(row + 8) * ldc + col) =
                    __floats2half2_rn(acc[mt][nt][2] + bx, acc[mt][nt][3] + by);
            } else {
                float* C = (float*)Cv;
                *(float2*)(C + (size_t)row * ldc + col) =
                    make_float2(acc[mt][nt][0] + bx, acc[mt][nt][1] + by);
                *(float2*)(C + (size_t)(row + 8) * ldc + col) =
                    make_float2(acc[mt][nt][2] + bx, acc[mt][nt][3] + by);
            }
        }
    }
}

// ---------------- conversion kernels -----------------------------------------
// x f32 -> fp16, with the QKV bias concat folded into the last block.
__global__ void cvt_f2h_bias(const float4* __restrict__ in, uint2* __restrict__ out, int n4,
                             const float* __restrict__ bq, const float* __restrict__ bk,
                             const float* __restrict__ bv, float* __restrict__ bo_cat)
{
    if (blockIdx.x == gridDim.x - 1) {
        for (int i = threadIdx.x; i < DIM; i += blockDim.x) {
            bo_cat[i] = bq[i];
            bo_cat[i + DIM] = bk[i];
            bo_cat[i + 2 * DIM] = bv[i];
        }
        return;
    }
    const int nb = gridDim.x - 1;
    for (int i = blockIdx.x * blockDim.x + threadIdx.x; i < n4; i += nb * blockDim.x) {
        float4 v = in[i];
        __half2 h01 = __floats2half2_rn(v.x, v.y);
        __half2 h23 = __floats2half2_rn(v.z, v.w);
        out[i] = make_uint2(*(uint32_t*)&h01, *(uint32_t*)&h23);
    }
}

// 4 weights: W[K][N] f32 -> WT[N][K] fp16
__global__ void cvt_wT4(const float* __restrict__ W0, const float* __restrict__ W1,
                        const float* __restrict__ W2, const float* __restrict__ W3,
                        __half* __restrict__ T)
{
    __shared__ float tile[32][33];
    const float* W = (blockIdx.z == 0) ? W0 : (blockIdx.z == 1) ? W1 : (blockIdx.z == 2) ? W2 : W3;
    __half* Tz = T + (size_t)blockIdx.z * DIM * DIM;
    int n0 = blockIdx.x * 32, k0 = blockIdx.y * 32;
    int tx = threadIdx.x, ty = threadIdx.y;
#pragma unroll
    for (int j = 0; j < 32; j += 8)
        tile[ty + j][tx] = W[(size_t)(k0 + ty + j) * DIM + n0 + tx];
    __syncthreads();
#pragma unroll
    for (int j = 0; j < 32; j += 8)
        Tz[(size_t)(n0 + ty + j) * DIM + k0 + tx] = __float2half_rn(tile[tx][ty + j]);
}

// ---------------- warp-per-node attention (register-only, zero smem) ---------
// Lane l holds elements [j*256 + 8l, 8l+8) of each of q/k/v => register group
// j IS head j spread across the warp. 16 scores via bfly reductions; softmax
// redundantly in every lane; output mixing entirely in registers.
__global__ __launch_bounds__(256)
void attn_kernel(const __half* __restrict__ QKV, __half* __restrict__ Ah)
{
    const int lane = threadIdx.x & 31;
    const int node = blockIdx.x * 8 + (threadIdx.x >> 5);

    const __half* q = QKV + (size_t)node * NQKV;
    const __half* k = q + DIM;
    const __half* v = q + 2 * DIM;

    float qf[4][8], kf[4][8];
#pragma unroll
    for (int j = 0; j < 4; j++) {
        uint4 tq = *(const uint4*)(q + j * HD + lane * 8);
        uint4 tk = *(const uint4*)(k + j * HD + lane * 8);
        const __half2* hq = (const __half2*)&tq;
        const __half2* hk = (const __half2*)&tk;
#pragma unroll
        for (int e = 0; e < 4; e++) {
            float2 fq = __half22float2(hq[e]);
            float2 fk = __half22float2(hk[e]);
            qf[j][2 * e] = fq.x; qf[j][2 * e + 1] = fq.y;
            kf[j][2 * e] = fk.x; kf[j][2 * e + 1] = fk.y;
        }
    }

    // 16 partial dots, then butterfly-reduce (all lanes get full sums)
    float sc[4][4];
#pragma unroll
    for (int h = 0; h < 4; h++)
#pragma unroll
        for (int g = 0; g < 4; g++) {
            float s = 0.f;
#pragma unroll
            for (int e = 0; e < 8; e++) s += qf[h][e] * kf[g][e];
            sc[h][g] = s;
        }
#pragma unroll
    for (int h = 0; h < 4; h++)
#pragma unroll
        for (int g = 0; g < 4; g++)
#pragma unroll
            for (int off = 16; off; off >>= 1)
                sc[h][g] += __shfl_xor_sync(0xffffffffu, sc[h][g], off);

    // softmax over g (every lane computes identically)
    float w[4][4];
#pragma unroll
    for (int h = 0; h < 4; h++) {
        float s0 = sc[h][0] * 0.0625f, s1 = sc[h][1] * 0.0625f;
        float s2 = sc[h][2] * 0.0625f, s3 = sc[h][3] * 0.0625f;
        float m = fmaxf(fmaxf(s0, s1), fmaxf(s2, s3));
        float e0 = __expf(s0 - m), e1 = __expf(s1 - m), e2 = __expf(s2 - m), e3 = __expf(s3 - m);
        float inv = 1.f / (e0 + e1 + e2 + e3);
        w[h][0] = e0 * inv; w[h][1] = e1 * inv; w[h][2] = e2 * inv; w[h][3] = e3 * inv;
    }

    // load v, mix, store
    float vf[4][8];
#pragma unroll
    for (int j = 0; j < 4; j++) {
        uint4 tv = *(const uint4*)(v + j * HD + lane * 8);
        const __half2* hv = (const __half2*)&tv;
#pragma unroll
        for (int e = 0; e < 4; e++) {
            float2 fv = __half22float2(hv[e]);
            vf[j][2 * e] = fv.x; vf[j][2 * e + 1] = fv.y;
        }
    }

    __half* o = g_ah == nullptr ? nullptr : Ah + (size_t)node * DIM;  // keep simple
#pragma unroll
    for (int h = 0; h < 4; h++) {
        uint4 pack;
        __half2* ph = (__half2*)&pack;
#pragma unroll
        for (int e = 0; e < 4; e++) {
            float x = w[h][0] * vf[0][2 * e]     + w[h][1] * vf[1][2 * e]
                    + w[h][2] * vf[2][2 * e]     + w[h][3] * vf[3][2 * e];
            float y = w[h][0] * vf[0][2 * e + 1] + w[h][1] * vf[1][2 * e + 1]
                    + w[h][2] * vf[2][2 * e + 1] + w[h][3] * vf[3][2 * e + 1];
            ph[e] = __floats2half2_rn(x, y);
        }
        *(uint4*)(o + h * HD + lane * 8) = pack;
    }
}

// ---------------- launch -----------------------------------------------------
extern "C" void kernel_launch(void* const* d_in, const int* in_sizes, int n_in,
                              void* d_out, int out_size)
{
    const float* x  = (const float*)d_in[0];
    const float* Wq = (const float*)d_in[2];
    const float* bq = (const float*)d_in[3];
    const float* Wk = (const float*)d_in[4];
    const float* bk = (const float*)d_in[5];
    const float* Wv = (const float*)d_in[6];
    const float* bv = (const float*)d_in[7];
    const float* Wo = (const float*)d_in[8];
    const float* bo = (const float*)d_in[9];
    float* out = (float*)d_out;

    __half *xh, *qkv, *ah, *wT;
    float* bqkv;
    cudaGetSymbolAddress((void**)&xh, g_xh);
    cudaGetSymbolAddress((void**)&qkv, g_qkv);
    cudaGetSymbolAddress((void**)&ah, g_ah);
    cudaGetSymbolAddress((void**)&wT, g_wT);
    cudaGetSymbolAddress((void**)&bqkv, g_bqkv);

    cudaFuncSetAttribute(gemm_h<true>,  cudaFuncAttributeMaxDynamicSharedMemorySize, GEMM_SMEM);
    cudaFuncSetAttribute(gemm_h<false>, cudaFuncAttributeMaxDynamicSharedMemorySize, GEMM_SMEM);

    const size_t WSZ = (size_t)DIM * DIM;

    cvt_f2h_bias<<<2049, 256>>>((const float4*)x, (uint2*)xh, M_ROWS * DIM / 4,
                                bq, bk, bv, bqkv);
    dim3 tgrid(32, 32, 4), tblk(32, 8);
    cvt_wT4<<<tgrid, tblk>>>(Wq, Wk, Wv, Wo, wT);

    // Fused QKV GEMM: B = wT rows [0, 3072), C = qkv [M, 3072]
    dim3 gQKV(NQKV / BN, M_ROWS / BM);  // (24, 256)
    gemm_h<true><<<gQKV, 128, GEMM_SMEM>>>(xh, wT, bqkv, qkv, NQKV);

    attn_kernel<<<M_ROWS / 8, 256>>>(qkv, ah);

    dim3 gO(DIM / BN, M_ROWS / BM);     // (8, 256)
    gemm_h<false><<<gO, 128, GEMM_SMEM>>>(ah, wT + 3 * WSZ, bo, out, DIM);
}

// round 17
// speedup vs baseline: 1.3522x; 1.0053x over previous
#include <cuda_runtime.h>
#include <cuda_fp16.h>
#include <cstdint>

#define M_ROWS (8 * 4096)
#define DIM 1024
#define NQKV 3072
#define NH 4
#define HD 256

#define BM 128
#define BN 128
#define BK 32
#define STAGES 4
#define KITERS (DIM / BK)                 // 32
#define A_BYTES (128 * 80)                // 10240
#define B_BYTES (128 * 80)                // 10240
#define STAGE_BYTES (A_BYTES + B_BYTES)   // 20480
#define GEMM_SMEM (STAGES * STAGE_BYTES)  // 81920

// ---------------- scratch (static device arrays; no allocation) -------------
__device__ __half g_xh[(size_t)M_ROWS * DIM];
__device__ __half g_qkv[(size_t)M_ROWS * NQKV];
__device__ __half g_ah[(size_t)M_ROWS * DIM];
__device__ __half g_wT[4][(size_t)DIM * DIM];
__device__ float  g_bqkv[NQKV];

// ---------------- PTX helpers ------------------------------------------------
__device__ __forceinline__ uint32_t smem_u32(const void* p) {
    uint32_t a;
    asm("{ .reg .u64 t; cvta.to.shared.u64 t, %1; cvt.u32.u64 %0, t; }" : "=r"(a) : "l"(p));
    return a;
}
#define CP16(dst, src) \
    asm volatile("cp.async.cg.shared.global [%0], [%1], 16;" :: "r"(dst), "l"(src))
#define CP_COMMIT() asm volatile("cp.async.commit_group;" ::: "memory")
#define CP_WAIT2()  asm volatile("cp.async.wait_group 2;" ::: "memory")

#define LDSM_X4(r, addr) \
    asm volatile("ldmatrix.sync.aligned.m8n8.x4.shared.b16 {%0,%1,%2,%3}, [%4];" \
        : "=r"((r)[0]), "=r"((r)[1]), "=r"((r)[2]), "=r"((r)[3]) : "r"(addr))

#define MMA16816(d, a, b) \
    asm volatile("mma.sync.aligned.m16n8k16.row.col.f32.f16.f16.f32 " \
        "{%0,%1,%2,%3}, {%4,%5,%6,%7}, {%8,%9}, {%0,%1,%2,%3};" \
        : "+f"((d)[0]), "+f"((d)[1]), "+f"((d)[2]), "+f"((d)[3]) \
        : "r"((a)[0]), "r"((a)[1]), "r"((a)[2]), "r"((a)[3]), "r"((b)[0]), "r"((b)[1]))

// ---------------- fp16 GEMM via mma.sync (R9 config — measured optimum) ------
template <bool OUT_HALF>
__global__ void __launch_bounds__(128, 2)
gemm_h(const __half* __restrict__ A, const __half* __restrict__ B,
       const float* __restrict__ bias, void* __restrict__ Cv, int ldc)
{
    extern __shared__ char sm[];
    const uint32_t sbase = smem_u32(sm);

    const int tid = threadIdx.x;
    const int wid = tid >> 5, lane = tid & 31;
    const int warp_m = wid & 1;
    const int warp_n = wid >> 1;
    const int rowBase = blockIdx.y * BM;
    const int colBase = blockIdx.x * BN;

    const int r0 = tid >> 2, c0 = tid & 3;
    const __half* gA = A + (size_t)(rowBase + r0) * DIM + c0 * 8;
    const __half* gB = B + (size_t)(colBase + r0) * DIM + c0 * 8;
    const uint32_t sOff = (uint32_t)(r0 * 80 + c0 * 16);

    float acc[4][8][4];
#pragma unroll
    for (int i = 0; i < 4; i++)
#pragma unroll
        for (int j = 0; j < 8; j++)
#pragma unroll
            for (int q = 0; q < 4; q++) acc[i][j][q] = 0.f;

    auto prefetch = [&](int s, int k0) {
        uint32_t sA = sbase + s * STAGE_BYTES;
        uint32_t sB = sA + A_BYTES;
        const __half* pa = gA + k0;
        const __half* pb = gB + k0;
#pragma unroll
        for (int j = 0; j < 4; j++) {
            CP16(sA + sOff + j * 32 * 80, pa + (size_t)j * 32 * DIM);
            CP16(sB + sOff + j * 32 * 80, pb + (size_t)j * 32 * DIM);
        }
        CP_COMMIT();
    };

#pragma unroll
    for (int s = 0; s < STAGES - 1; s++) prefetch(s, s * BK);

    const uint32_t aLane = (uint32_t)((warp_m * 64 + (lane & 15)) * 80 + (lane >> 4) * 16);
    const uint32_t bLane = (uint32_t)((warp_n * 64 + (lane & 7) + ((lane >> 4) << 3)) * 80 +
                                      ((lane >> 3) & 1) * 16);

    for (int i = 0; i < KITERS; i++) {
        CP_WAIT2();
        __syncthreads();
        if (i + STAGES - 1 < KITERS) prefetch((i + STAGES - 1) & (STAGES - 1), (i + STAGES - 1) * BK);
        else CP_COMMIT();

        const uint32_t st = sbase + (i & (STAGES - 1)) * STAGE_BYTES;
        const uint32_t aB = st + aLane;
        const uint32_t bB = st + A_BYTES + bLane;
#pragma unroll
        for (int kk = 0; kk < 2; kk++) {
            uint32_t af[4][4], bf[4][4];
#pragma unroll
            for (int mt = 0; mt < 4; mt++) LDSM_X4(af[mt], aB + mt * 16 * 80 + kk * 32);
#pragma unroll
            for (int p = 0; p < 4; p++)  LDSM_X4(bf[p], bB + p * 16 * 80 + kk * 32);
#pragma unroll
            for (int mt = 0; mt < 4; mt++)
#pragma unroll
                for (int nt = 0; nt < 8; nt++)
                    MMA16816(acc[mt][nt], af[mt], bf[nt >> 1] + (nt & 1) * 2);
        }
    }

    // epilogue
#pragma unroll
    for (int mt = 0; mt < 4; mt++) {
        const int row = rowBase + warp_m * 64 + mt * 16 + (lane >> 2);
#pragma unroll
        for (int nt = 0; nt < 8; nt++) {
            const int col = colBase + warp_n * 64 + nt * 8 + (lane & 3) * 2;
            const float bx = bias[col], by = bias[col + 1];
            if (OUT_HALF) {
                __half* C = (__half*)Cv;
                *(__half2*)(C + (size_t)row * ldc + col) =
                    __floats2half2_rn(acc[mt][nt][0] + bx, acc[mt][nt][1] + by);
                *(__half2*)(C + (size_t)(row + 8) * ldc + col) =
                    __floats2half2_rn(acc[mt][nt][2] + bx, acc[mt][nt][3] + by);
            } else {
                float* C = (float*)Cv;
                *(float2*)(C + (size_t)row * ldc + col) =
                    make_float2(acc[mt][nt][0] + bx, acc[mt][nt][1] + by);
                *(float2*)(C + (size_t)(row + 8) * ldc + col) =
                    make_float2(acc[mt][nt][2] + bx, acc[mt][nt][3] + by);
            }
        }
    }
}

// ---------------- fused conversion kernel ------------------------------------
// Blocks [0, NXB): x f32 -> fp16 (grid-stride).
// Blocks [NXB, NXB+4096): weight transpose W[K][N] f32 -> WT[N][K] fp16.
// Block NXB+4096: QKV bias concat.
#define NXB 2048
__global__ void cvt_all(const float4* __restrict__ xin, uint2* __restrict__ xout, int n4,
                        const float* __restrict__ W0, const float* __restrict__ W1,
                        const float* __restrict__ W2, const float* __restrict__ W3,
                        __half* __restrict__ T,
                        const float* __restrict__ bq, const float* __restrict__ bk,
                        const float* __restrict__ bv, float* __restrict__ bo_cat)
{
    const int b = blockIdx.x;
    if (b < NXB) {
        for (int i = b * blockDim.x + threadIdx.x; i < n4; i += NXB * blockDim.x) {
            float4 v = xin[i];
            __half2 h01 = __floats2half2_rn(v.x, v.y);
            __half2 h23 = __floats2half2_rn(v.z, v.w);
            xout[i] = make_uint2(*(uint32_t*)&h01, *(uint32_t*)&h23);
        }
        return;
    }
    if (b == NXB + 4096) {
        for (int i = threadIdx.x; i < DIM; i += blockDim.x) {
            bo_cat[i] = bq[i];
            bo_cat[i + DIM] = bk[i];
            bo_cat[i + 2 * DIM] = bv[i];
        }
        return;
    }
    // weight transpose: decode tile
    __shared__ float tile[32][33];
    const int idx = b - NXB;            // 0..4095
    const int z = idx >> 10;            // matrix 0..3
    const int t = idx & 1023;           // 0..1023
    const int bx = t & 31, by = t >> 5; // 32x32 tile grid
    const float* W = (z == 0) ? W0 : (z == 1) ? W1 : (z == 2) ? W2 : W3;
    __half* Tz = T + (size_t)z * DIM * DIM;
    const int n0 = bx * 32, k0 = by * 32;
    const int tx = threadIdx.x & 31, ty = threadIdx.x >> 5;  // 32 x 8
#pragma unroll
    for (int j = 0; j < 32; j += 8)
        tile[ty + j][tx] = W[(size_t)(k0 + ty + j) * DIM + n0 + tx];
    __syncthreads();
#pragma unroll
    for (int j = 0; j < 32; j += 8)
        Tz[(size_t)(n0 + ty + j) * DIM + k0 + tx] = __float2half_rn(tile[tx][ty + j]);
}

// ---------------- warp-per-node attention (register-only, zero smem) ---------
__global__ __launch_bounds__(256)
void attn_kernel(const __half* __restrict__ QKV, __half* __restrict__ Ah)
{
    const int lane = threadIdx.x & 31;
    const int node = blockIdx.x * 8 + (threadIdx.x >> 5);

    const __half* q = QKV + (size_t)node * NQKV;
    const __half* k = q + DIM;
    const __half* v = q + 2 * DIM;

    float qf[4][8], kf[4][8];
#pragma unroll
    for (int j = 0; j < 4; j++) {
        uint4 tq = *(const uint4*)(q + j * HD + lane * 8);
        uint4 tk = *(const uint4*)(k + j * HD + lane * 8);
        const __half2* hq = (const __half2*)&tq;
        const __half2* hk = (const __half2*)&tk;
#pragma unroll
        for (int e = 0; e < 4; e++) {
            float2 fq = __half22float2(hq[e]);
            float2 fk = __half22float2(hk[e]);
            qf[j][2 * e] = fq.x; qf[j][2 * e + 1] = fq.y;
            kf[j][2 * e] = fk.x; kf[j][2 * e + 1] = fk.y;
        }
    }

    float sc[4][4];
#pragma unroll
    for (int h = 0; h < 4; h++)
#pragma unroll
        for (int g = 0; g < 4; g++) {
            float s = 0.f;
#pragma unroll
            for (int e = 0; e < 8; e++) s += qf[h][e] * kf[g][e];
            sc[h][g] = s;
        }
#pragma unroll
    for (int h = 0; h < 4; h++)
#pragma unroll
        for (int g = 0; g < 4; g++)
#pragma unroll
            for (int off = 16; off; off >>= 1)
                sc[h][g] += __shfl_xor_sync(0xffffffffu, sc[h][g], off);

    float w[4][4];
#pragma unroll
    for (int h = 0; h < 4; h++) {
        float s0 = sc[h][0] * 0.0625f, s1 = sc[h][1] * 0.0625f;
        float s2 = sc[h][2] * 0.0625f, s3 = sc[h][3] * 0.0625f;
        float m = fmaxf(fmaxf(s0, s1), fmaxf(s2, s3));
        float e0 = __expf(s0 - m), e1 = __expf(s1 - m), e2 = __expf(s2 - m), e3 = __expf(s3 - m);
        float inv = 1.f / (e0 + e1 + e2 + e3);
        w[h][0] = e0 * inv; w[h][1] = e1 * inv; w[h][2] = e2 * inv; w[h][3] = e3 * inv;
    }

    float vf[4][8];
#pragma unroll
    for (int j = 0; j < 4; j++) {
        uint4 tv = *(const uint4*)(v + j * HD + lane * 8);
        const __half2* hv = (const __half2*)&tv;
#pragma unroll
        for (int e = 0; e < 4; e++) {
            float2 fv = __half22float2(hv[e]);
            vf[j][2 * e] = fv.x; vf[j][2 * e + 1] = fv.y;
        }
    }

    __half* o = Ah + (size_t)node * DIM;
#pragma unroll
    for (int h = 0; h < 4; h++) {
        uint4 pack;
        __half2* ph = (__half2*)&pack;
#pragma unroll
        for (int e = 0; e < 4; e++) {
            float x = w[h][0] * vf[0][2 * e]     + w[h][1] * vf[1][2 * e]
                    + w[h][2] * vf[2][2 * e]     + w[h][3] * vf[3][2 * e];
            float y = w[h][0] * vf[0][2 * e + 1] + w[h][1] * vf[1][2 * e + 1]
                    + w[h][2] * vf[2][2 * e + 1] + w[h][3] * vf[3][2 * e + 1];
            ph[e] = __floats2half2_rn(x, y);
        }
        *(uint4*)(o + h * HD + lane * 8) = pack;
    }
}

// ---------------- launch -----------------------------------------------------
extern "C" void kernel_launch(void* const* d_in, const int* in_sizes, int n_in,
                              void* d_out, int out_size)
{
    const float* x  = (const float*)d_in[0];
    const float* Wq = (const float*)d_in[2];
    const float* bq = (const float*)d_in[3];
    const float* Wk = (const float*)d_in[4];
    const float* bk = (const float*)d_in[5];
    const float* Wv = (const float*)d_in[6];
    const float* bv = (const float*)d_in[7];
    const float* Wo = (const float*)d_in[8];
    const float* bo = (const float*)d_in[9];
    float* out = (float*)d_out;

    __half *xh, *qkv, *ah, *wT;
    float* bqkv;
    cudaGetSymbolAddress((void**)&xh, g_xh);
    cudaGetSymbolAddress((void**)&qkv, g_qkv);
    cudaGetSymbolAddress((void**)&ah, g_ah);
    cudaGetSymbolAddress((void**)&wT, g_wT);
    cudaGetSymbolAddress((void**)&bqkv, g_bqkv);

    cudaFuncSetAttribute(gemm_h<true>,  cudaFuncAttributeMaxDynamicSharedMemorySize, GEMM_SMEM);
    cudaFuncSetAttribute(gemm_h<false>, cudaFuncAttributeMaxDynamicSharedMemorySize, GEMM_SMEM);

    const size_t WSZ = (size_t)DIM * DIM;

    // One fused conversion launch: x->fp16, 4 weight transposes, bias concat.
    cvt_all<<<NXB + 4096 + 1, 256>>>((const float4*)x, (uint2*)xh, M_ROWS * DIM / 4,
                                     Wq, Wk, Wv, Wo, wT, bq, bk, bv, bqkv);

    // Fused QKV GEMM: B = wT rows [0, 3072), C = qkv [M, 3072]
    dim3 gQKV(NQKV / BN, M_ROWS / BM);  // (24, 256)
    gemm_h<true><<<gQKV, 128, GEMM_SMEM>>>(xh, wT, bqkv, qkv, NQKV);

    attn_kernel<<<M_ROWS / 8, 256>>>(qkv, ah);

    dim3 gO(DIM / BN, M_ROWS / BM);     // (8, 256)
    gemm_h<false><<<gO, 128, GEMM_SMEM>>>(ah, wT + 3 * WSZ, bo, out, DIM);
}